// round 11
// baseline (speedup 1.0000x reference)
#include <cuda_runtime.h>
#include <cstdint>
#include <math.h>

#define Bb 8
#define Ss 2048
#define Hh 1024
#define NEGV (-1e12f)

// ---------------- mma.sync tf32 GEMM configuration -----------------------------------
// 128x128 CTA tile, 256 threads (8 warps, 64x32 warp tiles), 3-stage bulk-copy pipeline,
// 110.6 KB smem x 2 CTAs/SM = 16 warps/SM.
// R10 lever: all GEMM operands stored K-PERMUTED within 8-element groups
// (elem e -> pos e<4 ? 2e : 2(e-4)+1), so each mma fragment k-pair (tig, tig+4)
// is one contiguous float2 -> LDS.64. Halves LDS instruction count + address ALU.
constexpr int BM = 128, BN = 128, BKT = 32;
constexpr int ROWB = 36 * 4;                       // smem row pitch: 32 floats + 4 pad = 144B
constexpr int ABYTES = BM * ROWB;                  // 18432
constexpr int BBYTES = BN * ROWB;                  // 18432
constexpr int STAGE  = ABYTES + BBYTES;            // 36864
constexpr int NSTG   = 3;
constexpr int DYN_SMEM = NSTG * STAGE;             // 110592

// ---------------- scratch (static device memory) -------------------------------------
__device__ float g_xr [(size_t)Bb * Ss * Hh];      // x, k-permuted along Hh
__device__ float g_q  [(size_t)Bb * Ss * Hh];      // permuted along Hh
__device__ float g_k  [(size_t)Bb * Ss * Hh];      // permuted along Hh
__device__ float g_v  [(size_t)Bb * Ss * Hh];      // permuted along Hh (un-permuted by vtrans)
__device__ float g_vt [(size_t)Bb * Ss * Hh];      // v^T, permuted along Ss
__device__ float g_ctx[(size_t)Bb * Ss * Hh];      // permuted along Hh
__device__ float g_attnp[(size_t)Bb * Ss * Ss];    // softmax(attn), permuted along key-Ss
__device__ float g_wq[Hh * Hh], g_wk[Hh * Hh], g_wv[Hh * Hh], g_wa[Hh * Hh];  // permuted along Hh

// element e (within 8-group) lives at position perm8; works on 0..31 indices too
__device__ __forceinline__ int perm8(int i) {
    int e = i & 7;
    return (i & ~7) | ((e < 4) ? (e << 1) : ((e << 1) - 7));
}

// ---------------- helpers --------------------------------------------------------------
__device__ __forceinline__ uint32_t smem_u32(const void* p) {
    uint32_t a;
    asm("{ .reg .u64 t; cvta.to.shared.u64 t, %1; cvt.u32.u64 %0, t; }" : "=r"(a) : "l"(p));
    return a;
}
__device__ __forceinline__ float tf32r(float x) {
    uint32_t u;
    asm("cvt.rna.tf32.f32 %0, %1;" : "=r"(u) : "f"(x));
    return __uint_as_float(u);
}

#define MBARRIER_INIT(addr, cnt) \
    asm volatile("mbarrier.init.shared.b64 [%0], %1;" :: "r"((uint32_t)(addr)), "r"((uint32_t)(cnt)) : "memory")

#define MBARRIER_WAIT_PARITY(mbar_smem_addr, phase_parity) do {                         \
    uint32_t _mbar = (uint32_t)(mbar_smem_addr);                                        \
    uint32_t _parity = (uint32_t)(phase_parity);                                        \
    uint32_t _done;                                                                     \
    asm volatile("{\n\t.reg .pred p;\n\t"                                               \
        "mbarrier.try_wait.parity.acquire.cta.shared::cta.b64 p, [%1], %2;\n\t"         \
        "selp.b32 %0, 1, 0, p;\n\t}"                                                    \
        : "=r"(_done) : "r"(_mbar), "r"(_parity) : "memory");                           \
    if (!_done) {                                                                       \
        asm volatile("{\n\t.reg .pred P1;\n\t"                                          \
            "WAIT_LOOP_%=:\n\t"                                                         \
            "mbarrier.try_wait.parity.acquire.cta.shared::cta.b64 P1, [%0], %1, 0x989680;\n\t" \
            "@P1 bra.uni WAIT_DONE_%=;\n\t"                                             \
            "bra.uni WAIT_LOOP_%=;\n\t"                                                 \
            "WAIT_DONE_%=:\n\t}"                                                        \
            :: "r"(_mbar), "r"(_parity) : "memory");                                    \
    }                                                                                   \
} while (0)

// bulk async copy: 1 instruction per 128B row, completion via mbarrier tx-bytes
__device__ __forceinline__ void blk_cpy(uint32_t dst, const float* src, uint32_t mbar) {
    asm volatile(
        "cp.async.bulk.shared::cta.global.mbarrier::complete_tx::bytes [%0], [%1], %2, [%3];"
        :: "r"(dst), "l"(src), "r"(128), "r"(mbar) : "memory");
}
__device__ __forceinline__ void arrive_tx(uint32_t mbar, uint32_t bytes) {
    asm volatile("mbarrier.arrive.expect_tx.shared.b64 _, [%0], %1;"
                 :: "r"(mbar), "r"(bytes) : "memory");
}

__device__ __forceinline__ void mma8(float d[4], const uint32_t a[4], const uint32_t b[2]) {
    asm volatile(
        "mma.sync.aligned.m16n8k8.row.col.f32.tf32.tf32.f32 "
        "{%0,%1,%2,%3}, {%4,%5,%6,%7}, {%8,%9}, {%0,%1,%2,%3};"
        : "+f"(d[0]), "+f"(d[1]), "+f"(d[2]), "+f"(d[3])
        : "r"(a[0]), "r"(a[1]), "r"(a[2]), "r"(a[3]), "r"(b[0]), "r"(b[1]));
}

// ---------------- GEMM mainloop: acc[4][4][4] = A[bm:bm+128] * B[bn:bn+128]^T ---------
// A: [M,K] row-major K-PERMUTED, B: [N,K] row-major K-PERMUTED (computes A @ B^T).
// 256 threads, 8 warps as 2(M) x 4(N); warp tile 64x32.
__device__ __forceinline__ void gemm_loop(const float* __restrict__ A,
                                          const float* __restrict__ B,
                                          int K, int lda, int ldb, int bm, int bn,
                                          float acc[4][4][4]) {
    extern __shared__ __align__(16) char dsm[];
    __shared__ __align__(8) unsigned long long mbar[NSTG];
    const int tid = threadIdx.x;
    const int wid = tid >> 5, lane = tid & 31;
    const int gid = lane >> 2, tig = lane & 3;
    const int wm = (wid & 1) * 64, wn = (wid >> 1) * 32;
    const int NK = K / BKT;

#pragma unroll
    for (int mi = 0; mi < 4; mi++)
#pragma unroll
        for (int ni = 0; ni < 4; ni++)
#pragma unroll
            for (int j = 0; j < 4; j++) acc[mi][ni][j] = 0.0f;

    const uint32_t sbase = smem_u32(dsm);

    if (tid == 0) {
#pragma unroll
        for (int s = 0; s < NSTG; s++) MBARRIER_INIT(smem_u32(&mbar[s]), 256);
    }
    __syncthreads();

    // threads 0-127 copy A rows, threads 128-255 copy B rows (128B each)
    auto issue = [&](int s, int kt) {
        const uint32_t m = smem_u32(&mbar[s]);
        const uint32_t st = sbase + s * STAGE;
        arrive_tx(m, 128u);
        if (tid < 128) {
            blk_cpy(st + tid * ROWB, A + (size_t)(bm + tid) * lda + kt * BKT, m);
        } else {
            const int r = tid - 128;
            blk_cpy(st + ABYTES + r * ROWB, B + (size_t)(bn + r) * ldb + kt * BKT, m);
        }
    };

    issue(0, 0);
    issue(1, 1);

    for (int kt = 0; kt < NK; kt++) {
        const int s = kt % NSTG;
        MBARRIER_WAIT_PARITY(smem_u32(&mbar[s]), (kt / NSTG) & 1);

        const float* As = (const float*)(dsm + s * STAGE);
        const float* Bs = (const float*)(dsm + s * STAGE + ABYTES);
#pragma unroll
        for (int kk = 0; kk < 4; kk++) {
            uint32_t a[4][4], b[4][2];
#pragma unroll
            for (int mi = 0; mi < 4; mi++) {
                // k-permuted: float2 at pos 2*tig = (elem tig, elem tig+4)
                const float2* p0 = (const float2*)(As + (wm + mi * 16 + gid) * 36 + kk * 8) + tig;
                const float2* p1 = p0 + 4 * 36;        // +8 rows
                float2 fa0 = p0[0];
                float2 fa1 = p1[0];
                a[mi][0] = __float_as_uint(fa0.x);
                a[mi][1] = __float_as_uint(fa1.x);
                a[mi][2] = __float_as_uint(fa0.y);
                a[mi][3] = __float_as_uint(fa1.y);
            }
#pragma unroll
            for (int ni = 0; ni < 4; ni++) {
                const float2* p = (const float2*)(Bs + (wn + ni * 8 + gid) * 36 + kk * 8) + tig;
                float2 fb = p[0];
                b[ni][0] = __float_as_uint(fb.x);
                b[ni][1] = __float_as_uint(fb.y);
            }
#pragma unroll
            for (int mi = 0; mi < 4; mi++)
#pragma unroll
                for (int ni = 0; ni < 4; ni++)
                    mma8(acc[mi][ni], a[mi], b[ni]);
        }
        __syncthreads();   // all warps done with stage s before it is refilled
        if (kt + 2 < NK) issue((kt + 2) % NSTG, kt + 2);
    }
}

// fragment -> global coordinates helper values
#define EPI_SETUP()                                        \
    const int tid = threadIdx.x;                           \
    const int wid = tid >> 5, lane = tid & 31;             \
    const int gid = lane >> 2, tig = lane & 3;             \
    const int wm = (wid & 1) * 64, wn = (wid >> 1) * 32;   \
    const int bm = blockIdx.y * BM, bn = blockIdx.x * BN;  \
    const int pp = (tig < 2) ? (4 * tig) : (4 * tig - 7);  \
    (void)bm; (void)bn; (void)pp;

// ---------------- GEMM kernels ---------------------------------------------------------

// q/k/v = round_tf32((x_r @ W^T + b) * scale), stored K-PERMUTED along Hh
__global__ __launch_bounds__(256, 2) void qkv_tc(const float* __restrict__ bq,
                                                 const float* __restrict__ bk,
                                                 const float* __restrict__ bv) {
    EPI_SETUP();
    const float* W; const float* bias; float* out; float scale;
    if (blockIdx.z == 0)      { W = g_wq; bias = bq; out = g_q; scale = 1.0f / 32.0f; }
    else if (blockIdx.z == 1) { W = g_wk; bias = bk; out = g_k; scale = 1.0f; }
    else                      { W = g_wv; bias = bv; out = g_v; scale = 1.0f; }

    float acc[4][4][4];
    gemm_loop(g_xr, W, Hh, Hh, Hh, bm, bn, acc);

#pragma unroll
    for (int mi = 0; mi < 4; mi++) {
        const int r0 = bm + wm + mi * 16 + gid;
        float* o0 = out + (size_t)r0 * Hh;
        float* o1 = o0 + 8 * Hh;
#pragma unroll
        for (int ni = 0; ni < 4; ni++) {
            const int gb  = bn + wn + ni * 8;            // 8-aligned group base
            const int col = gb + 2 * tig;                // canonical element index
            float2 bv2 = *(const float2*)(bias + col);
            float w0x = tf32r((acc[mi][ni][0] + bv2.x) * scale);
            float w0y = tf32r((acc[mi][ni][1] + bv2.y) * scale);
            float w1x = tf32r((acc[mi][ni][2] + bv2.x) * scale);
            float w1y = tf32r((acc[mi][ni][3] + bv2.y) * scale);
            o0[gb + pp]     = w0x;                       // permuted positions
            o0[gb + pp + 2] = w0y;
            o1[gb + pp]     = w1x;
            o1[gb + pp + 2] = w1y;
        }
    }
}

// scores = q @ k^T + attn_bias, masked -> attn buffer (pre-softmax fp32, CANONICAL)
__global__ __launch_bounds__(256, 2) void scores_tc(const float* __restrict__ attn_bias,
                                                    const int* __restrict__ mask,
                                                    float* __restrict__ attn) {
    EPI_SETUP();
    const int b = blockIdx.z;
    float acc[4][4][4];
    gemm_loop(g_q + (size_t)b * Ss * Hh, g_k + (size_t)b * Ss * Hh,
              Hh, Hh, Hh, bm, bn, acc);

#pragma unroll
    for (int mi = 0; mi < 4; mi++) {
        const int r0 = bm + wm + mi * 16 + gid;
        const int r1 = r0 + 8;
        float* c0 = attn + ((size_t)b * Ss + r0) * Ss;
        float* c1 = attn + ((size_t)b * Ss + r1) * Ss;
        const float* ab0 = attn_bias + ((size_t)b * Ss + r0) * Ss;
        const float* ab1 = attn_bias + ((size_t)b * Ss + r1) * Ss;
        const int* m0 = mask + (size_t)r0 * Ss;
        const int* m1 = mask + (size_t)r1 * Ss;
#pragma unroll
        for (int ni = 0; ni < 4; ni++) {
            const int col = bn + wn + ni * 8 + 2 * tig;
            float2 b0 = *(const float2*)(ab0 + col);
            float2 b1 = *(const float2*)(ab1 + col);
            int2 k0 = *(const int2*)(m0 + col);
            int2 k1 = *(const int2*)(m1 + col);
            float2 w0, w1;
            w0.x = k0.x ? acc[mi][ni][0] + b0.x : NEGV;
            w0.y = k0.y ? acc[mi][ni][1] + b0.y : NEGV;
            w1.x = k1.x ? acc[mi][ni][2] + b1.x : NEGV;
            w1.y = k1.y ? acc[mi][ni][3] + b1.y : NEGV;
            *(float2*)(c0 + col) = w0;
            *(float2*)(c1 + col) = w1;
        }
    }
}

// ctx = round_tf32(attn @ vT^T), stored K-PERMUTED along Hh
__global__ __launch_bounds__(256, 2) void av_tc() {
    EPI_SETUP();
    const int b = blockIdx.z;
    float acc[4][4][4];
    gemm_loop(g_attnp + (size_t)b * Ss * Ss, g_vt + (size_t)b * Hh * Ss,
              Ss, Ss, Ss, bm, bn, acc);

#pragma unroll
    for (int mi = 0; mi < 4; mi++) {
        const int r0 = bm + wm + mi * 16 + gid;
        float* o0 = g_ctx + ((size_t)b * Ss + r0) * Hh;
        float* o1 = o0 + 8 * Hh;
#pragma unroll
        for (int ni = 0; ni < 4; ni++) {
            const int gb = bn + wn + ni * 8;
            o0[gb + pp]     = tf32r(acc[mi][ni][0]);
            o0[gb + pp + 2] = tf32r(acc[mi][ni][1]);
            o1[gb + pp]     = tf32r(acc[mi][ni][2]);
            o1[gb + pp + 2] = tf32r(acc[mi][ni][3]);
        }
    }
}

// out = ctx @ Wa^T + ba + residual(x)   (CANONICAL output)
__global__ __launch_bounds__(256, 2) void proj_tc(const float* __restrict__ ba,
                                                  const float* __restrict__ x,
                                                  float* __restrict__ out) {
    EPI_SETUP();
    float acc[4][4][4];
    gemm_loop(g_ctx, g_wa, Hh, Hh, Hh, bm, bn, acc);

#pragma unroll
    for (int mi = 0; mi < 4; mi++) {
        const int r0 = bm + wm + mi * 16 + gid;
        float* o0 = out + (size_t)r0 * Hh;
        float* o1 = o0 + 8 * Hh;
        const float* x0 = x + (size_t)r0 * Hh;
        const float* x1 = x0 + 8 * Hh;
#pragma unroll
        for (int ni = 0; ni < 4; ni++) {
            const int col = bn + wn + ni * 8 + 2 * tig;
            float2 bv2 = *(const float2*)(ba + col);
            float2 r0v = *(const float2*)(x0 + col);
            float2 r1v = *(const float2*)(x1 + col);
            float2 w0, w1;
            w0.x = acc[mi][ni][0] + bv2.x + r0v.x;
            w0.y = acc[mi][ni][1] + bv2.y + r0v.y;
            w1.x = acc[mi][ni][2] + bv2.x + r1v.x;
            w1.y = acc[mi][ni][3] + bv2.y + r1v.y;
            *(float2*)(o0 + col) = w0;
            *(float2*)(o1 + col) = w1;
        }
    }
}

// ---------------- small kernels ----------------------------------------------------------

// fused tf32-rounding + K-PERMUTING copy of x, Wq, Wk, Wv, Wa.
// thread i handles one 8-element group (two float4): out0=(e0,e4,e1,e5), out1=(e2,e6,e3,e7)
__global__ __launch_bounds__(256) void rcopy_all(const float4* __restrict__ x,
                                                 const float4* __restrict__ wq,
                                                 const float4* __restrict__ wk,
                                                 const float4* __restrict__ wv,
                                                 const float4* __restrict__ wa) {
    const int NX = (Bb * Ss * Hh) / 8;        // groups in x
    const int NW = (Hh * Hh) / 8;             // groups per weight
    int i = blockIdx.x * blockDim.x + threadIdx.x;
    const float4* s;
    float4* d;
    if (i < NX) {
        s = x + 2 * (size_t)i; d = (float4*)g_xr + 2 * (size_t)i;
    } else {
        int u = i - NX;
        int w = u / NW, idx = u - w * NW;
        const float4* srcs[4] = {wq, wk, wv, wa};
        float4* dsts[4] = {(float4*)g_wq, (float4*)g_wk, (float4*)g_wv, (float4*)g_wa};
        s = srcs[w] + 2 * (size_t)idx; d = dsts[w] + 2 * (size_t)idx;
    }
    float4 a = s[0], b = s[1];
    a.x = tf32r(a.x); a.y = tf32r(a.y); a.z = tf32r(a.z); a.w = tf32r(a.w);
    b.x = tf32r(b.x); b.y = tf32r(b.y); b.z = tf32r(b.z); b.w = tf32r(b.w);
    float4 o0 = make_float4(a.x, b.x, a.y, b.y);
    float4 o1 = make_float4(a.z, b.z, a.w, b.w);
    d[0] = o0;
    d[1] = o1;
}

// vt[b][h][s]: reads g_v (permuted along Hh), writes g_vt permuted along Ss
__global__ void vtrans_kernel() {
    __shared__ float t[32][33];
    const int b = blockIdx.z;
    const int s0 = blockIdx.x * 32, h0 = blockIdx.y * 32;
    const float* src = g_v + (size_t)b * Ss * Hh;
    float* dst = g_vt + (size_t)b * Hh * Ss;
    const int tx = threadIdx.x, ty = threadIdx.y;
    const int px = perm8(tx);
#pragma unroll
    for (int i = 0; i < 32; i += 8)
        t[ty + i][tx] = src[(size_t)(s0 + ty + i) * Hh + h0 + px];   // un-permute read
    __syncthreads();
#pragma unroll
    for (int i = 0; i < 32; i += 8)
        dst[(size_t)(h0 + ty + i) * Ss + s0 + px] = t[tx][ty + i];   // permute write
}

__device__ __forceinline__ float warpMax(float v) {
#pragma unroll
    for (int o = 16; o; o >>= 1) v = fmaxf(v, __shfl_xor_sync(0xffffffffu, v, o));
    return v;
}
__device__ __forceinline__ float warpSum(float v) {
#pragma unroll
    for (int o = 16; o; o >>= 1) v += __shfl_xor_sync(0xffffffffu, v, o);
    return v;
}
__device__ __forceinline__ float blockMax(float v) {
    __shared__ float sh[8];
    v = warpMax(v);
    if ((threadIdx.x & 31) == 0) sh[threadIdx.x >> 5] = v;
    __syncthreads();
    float r = fmaxf(fmaxf(fmaxf(sh[0], sh[1]), fmaxf(sh[2], sh[3])),
                    fmaxf(fmaxf(sh[4], sh[5]), fmaxf(sh[6], sh[7])));
    __syncthreads();
    return r;
}
__device__ __forceinline__ float blockSum(float v) {
    __shared__ float sh[8];
    v = warpSum(v);
    if ((threadIdx.x & 31) == 0) sh[threadIdx.x >> 5] = v;
    __syncthreads();
    float r = sh[0] + sh[1] + sh[2] + sh[3] + sh[4] + sh[5] + sh[6] + sh[7];
    __syncthreads();
    return r;
}

// softmax over S=2048; each thread owns one 8-element group (elements 8t..8t+7).
// Writes canonical rounded attn (output) AND k-permuted copy to g_attnp (for av GEMM).
__global__ __launch_bounds__(256) void softmax_kernel(float* __restrict__ attn) {
    size_t row = blockIdx.x;
    float4* p  = (float4*)(attn + row * Ss);
    float4* pp = (float4*)(g_attnp + row * Ss);
    int tid = threadIdx.x;
    float4 v0 = p[2 * tid];
    float4 v1 = p[2 * tid + 1];
    float m = fmaxf(fmaxf(fmaxf(v0.x, v0.y), fmaxf(v0.z, v0.w)),
                    fmaxf(fmaxf(v1.x, v1.y), fmaxf(v1.z, v1.w)));
    m = blockMax(m);
    v0.x = __expf(v0.x - m); v0.y = __expf(v0.y - m);
    v0.z = __expf(v0.z - m); v0.w = __expf(v0.w - m);
    v1.x = __expf(v1.x - m); v1.y = __expf(v1.y - m);
    v1.z = __expf(v1.z - m); v1.w = __expf(v1.w - m);
    float s = v0.x + v0.y + v0.z + v0.w + v1.x + v1.y + v1.z + v1.w;
    s = blockSum(s);
    float inv = 1.0f / s;
    v0.x = tf32r(v0.x * inv); v0.y = tf32r(v0.y * inv);
    v0.z = tf32r(v0.z * inv); v0.w = tf32r(v0.w * inv);
    v1.x = tf32r(v1.x * inv); v1.y = tf32r(v1.y * inv);
    v1.z = tf32r(v1.z * inv); v1.w = tf32r(v1.w * inv);
    p[2 * tid]     = v0;                              // canonical output
    p[2 * tid + 1] = v1;
    pp[2 * tid]     = make_float4(v0.x, v1.x, v0.y, v1.y);   // permuted copy
    pp[2 * tid + 1] = make_float4(v0.z, v1.z, v0.w, v1.w);
}

// in-place LayerNorm over H=1024 (biased variance, eps=1e-6)
__global__ __launch_bounds__(256) void ln_kernel(float* __restrict__ out,
                                                 const float* __restrict__ gamma,
                                                 const float* __restrict__ beta) {
    size_t row = blockIdx.x;
    float4* p = (float4*)(out + row * Hh);
    int tid = threadIdx.x;
    float4 v = p[tid];
    float s = v.x + v.y + v.z + v.w;
    s = blockSum(s);
    float mu = s * (1.0f / Hh);
    float dx = v.x - mu, dy = v.y - mu, dz = v.z - mu, dw = v.w - mu;
    float sq = dx * dx + dy * dy + dz * dz + dw * dw;
    sq = blockSum(sq);
    float rstd = rsqrtf(sq * (1.0f / Hh) + 1e-6f);
    float4 g = ((const float4*)gamma)[tid];
    float4 bt = ((const float4*)beta)[tid];
    v.x = dx * rstd * g.x + bt.x;
    v.y = dy * rstd * g.y + bt.y;
    v.z = dz * rstd * g.z + bt.z;
    v.w = dw * rstd * g.w + bt.w;
    p[tid] = v;
}

// ---------------- launch --------------------------------------------------------------
extern "C" void kernel_launch(void* const* d_in, const int* in_sizes, int n_in,
                              void* d_out, int out_size) {
    const float* x         = (const float*)d_in[0];
    const int*   mask      = (const int*)  d_in[1];
    const float* attn_bias = (const float*)d_in[2];
    const float* Wq = (const float*)d_in[3];  const float* bq = (const float*)d_in[4];
    const float* Wk = (const float*)d_in[5];  const float* bk = (const float*)d_in[6];
    const float* Wv = (const float*)d_in[7];  const float* bv = (const float*)d_in[8];
    const float* Wa = (const float*)d_in[9];  const float* ba = (const float*)d_in[10];
    const float* gamma = (const float*)d_in[11];
    const float* beta  = (const float*)d_in[12];

    float* out  = (float*)d_out;
    float* attn = out + (size_t)Bb * Ss * Hh;   // tuple (out, attn)

    cudaFuncSetAttribute(qkv_tc,    cudaFuncAttributeMaxDynamicSharedMemorySize, DYN_SMEM);
    cudaFuncSetAttribute(scores_tc, cudaFuncAttributeMaxDynamicSharedMemorySize, DYN_SMEM);
    cudaFuncSetAttribute(av_tc,     cudaFuncAttributeMaxDynamicSharedMemorySize, DYN_SMEM);
    cudaFuncSetAttribute(proj_tc,   cudaFuncAttributeMaxDynamicSharedMemorySize, DYN_SMEM);

    // 1 launch: round + k-permute all GEMM operands (groups of 8 elements)
    int ng = (Bb * Ss * Hh + 4 * Hh * Hh) / 8;
    rcopy_all<<<(ng + 255) / 256, 256>>>((const float4*)x, (const float4*)Wq,
                                         (const float4*)Wk, (const float4*)Wv,
                                         (const float4*)Wa);

    qkv_tc<<<dim3(Hh / BN, (Bb * Ss) / BM, 3), 256, DYN_SMEM>>>(bq, bk, bv);
    vtrans_kernel<<<dim3(Ss / 32, Hh / 32, Bb), dim3(32, 8)>>>();
    scores_tc<<<dim3(Ss / BN, Ss / BM, Bb), 256, DYN_SMEM>>>(attn_bias, mask, attn);
    softmax_kernel<<<Bb * Ss, 256>>>(attn);
    av_tc<<<dim3(Hh / BN, Ss / BM, Bb), 256, DYN_SMEM>>>();
    proj_tc<<<dim3(Hh / BN, (Bb * Ss) / BM), 256, DYN_SMEM>>>(ba, x, out);
    ln_kernel<<<Bb * Ss, 256>>>(out, gamma, beta);
}

// round 12
// speedup vs baseline: 1.1103x; 1.1103x over previous
#include <cuda_runtime.h>
#include <cstdint>
#include <math.h>

#define Bb 8
#define Ss 2048
#define Hh 1024
#define NEGV (-1e12f)

// ---------------- mma.sync tf32 GEMM configuration -----------------------------------
// 128x128 CTA tile, 256 threads (8 warps, 64x32 warp tiles), 3-stage bulk-copy pipeline,
// 110.6 KB smem x 2 CTAs/SM = 16 warps/SM.
// R11 lever: fragment loads via ldmatrix.m8n8.x4 (LDSM) instead of 96 scalar LDS.32:
// 24 instructions/warp/ktile, near-zero address ALU, conflict-free at 144B row pitch
// (36i mod 32 = 4i -> each 8-row matrix hits all 32 banks once).
constexpr int BM = 128, BN = 128, BKT = 32;
constexpr int ROWB = 36 * 4;                       // smem row pitch: 32 floats + 4 pad = 144B
constexpr int ABYTES = BM * ROWB;                  // 18432
constexpr int BBYTES = BN * ROWB;                  // 18432
constexpr int STAGE  = ABYTES + BBYTES;            // 36864
constexpr int NSTG   = 3;
constexpr int DYN_SMEM = NSTG * STAGE;             // 110592

// ---------------- scratch (static device memory) -------------------------------------
__device__ float g_xr [(size_t)Bb * Ss * Hh];
__device__ float g_q  [(size_t)Bb * Ss * Hh];
__device__ float g_k  [(size_t)Bb * Ss * Hh];
__device__ float g_v  [(size_t)Bb * Ss * Hh];
__device__ float g_vt [(size_t)Bb * Ss * Hh];
__device__ float g_ctx[(size_t)Bb * Ss * Hh];
__device__ float g_wq[Hh * Hh], g_wk[Hh * Hh], g_wv[Hh * Hh], g_wa[Hh * Hh];

// ---------------- helpers --------------------------------------------------------------
__device__ __forceinline__ uint32_t smem_u32(const void* p) {
    uint32_t a;
    asm("{ .reg .u64 t; cvta.to.shared.u64 t, %1; cvt.u32.u64 %0, t; }" : "=r"(a) : "l"(p));
    return a;
}
__device__ __forceinline__ float tf32r(float x) {
    uint32_t u;
    asm("cvt.rna.tf32.f32 %0, %1;" : "=r"(u) : "f"(x));
    return __uint_as_float(u);
}

#define MBARRIER_INIT(addr, cnt) \
    asm volatile("mbarrier.init.shared.b64 [%0], %1;" :: "r"((uint32_t)(addr)), "r"((uint32_t)(cnt)) : "memory")

#define MBARRIER_WAIT_PARITY(mbar_smem_addr, phase_parity) do {                         \
    uint32_t _mbar = (uint32_t)(mbar_smem_addr);                                        \
    uint32_t _parity = (uint32_t)(phase_parity);                                        \
    uint32_t _done;                                                                     \
    asm volatile("{\n\t.reg .pred p;\n\t"                                               \
        "mbarrier.try_wait.parity.acquire.cta.shared::cta.b64 p, [%1], %2;\n\t"         \
        "selp.b32 %0, 1, 0, p;\n\t}"                                                    \
        : "=r"(_done) : "r"(_mbar), "r"(_parity) : "memory");                           \
    if (!_done) {                                                                       \
        asm volatile("{\n\t.reg .pred P1;\n\t"                                          \
            "WAIT_LOOP_%=:\n\t"                                                         \
            "mbarrier.try_wait.parity.acquire.cta.shared::cta.b64 P1, [%0], %1, 0x989680;\n\t" \
            "@P1 bra.uni WAIT_DONE_%=;\n\t"                                             \
            "bra.uni WAIT_LOOP_%=;\n\t"                                                 \
            "WAIT_DONE_%=:\n\t}"                                                        \
            :: "r"(_mbar), "r"(_parity) : "memory");                                    \
    }                                                                                   \
} while (0)

// bulk async copy: 1 instruction per 128B row, completion via mbarrier tx-bytes
__device__ __forceinline__ void blk_cpy(uint32_t dst, const float* src, uint32_t mbar) {
    asm volatile(
        "cp.async.bulk.shared::cta.global.mbarrier::complete_tx::bytes [%0], [%1], %2, [%3];"
        :: "r"(dst), "l"(src), "r"(128), "r"(mbar) : "memory");
}
__device__ __forceinline__ void arrive_tx(uint32_t mbar, uint32_t bytes) {
    asm volatile("mbarrier.arrive.expect_tx.shared.b64 _, [%0], %1;"
                 :: "r"(mbar), "r"(bytes) : "memory");
}

#define LDSM_X4(r0, r1, r2, r3, addr) \
    asm volatile("ldmatrix.sync.aligned.m8n8.x4.shared.b16 {%0,%1,%2,%3}, [%4];" \
                 : "=r"(r0), "=r"(r1), "=r"(r2), "=r"(r3) : "r"(addr))

__device__ __forceinline__ void mma8(float d[4], const uint32_t a[4], const uint32_t b[2]) {
    asm volatile(
        "mma.sync.aligned.m16n8k8.row.col.f32.tf32.tf32.f32 "
        "{%0,%1,%2,%3}, {%4,%5,%6,%7}, {%8,%9}, {%0,%1,%2,%3};"
        : "+f"(d[0]), "+f"(d[1]), "+f"(d[2]), "+f"(d[3])
        : "r"(a[0]), "r"(a[1]), "r"(a[2]), "r"(a[3]), "r"(b[0]), "r"(b[1]));
}

// ---------------- GEMM mainloop: acc[4][4][4] = A[bm:bm+128] * B[bn:bn+128]^T ---------
// A: [M,K] row-major, B: [N,K] row-major (computes A @ B^T).
// 256 threads, 8 warps as 2(M) x 4(N); warp tile 64x32. Fragments via ldmatrix.x4.
__device__ __forceinline__ void gemm_loop(const float* __restrict__ A,
                                          const float* __restrict__ B,
                                          int K, int lda, int ldb, int bm, int bn,
                                          float acc[4][4][4]) {
    extern __shared__ __align__(16) char dsm[];
    __shared__ __align__(8) unsigned long long mbar[NSTG];
    const int tid = threadIdx.x;
    const int wid = tid >> 5, lane = tid & 31;
    const int wm = (wid & 1) * 64, wn = (wid >> 1) * 32;
    const int NK = K / BKT;

#pragma unroll
    for (int mi = 0; mi < 4; mi++)
#pragma unroll
        for (int ni = 0; ni < 4; ni++)
#pragma unroll
            for (int j = 0; j < 4; j++) acc[mi][ni][j] = 0.0f;

    const uint32_t sbase = smem_u32(dsm);
    // ldmatrix per-lane address parts: lanes 0-7 -> rows 0-7 seg0 (m0), 8-15 -> rows 8-15
    // seg0 (m1), 16-23 -> rows 0-7 seg1 (m2), 24-31 -> rows 8-15 seg1 (m3).
    const uint32_t lrow = (lane & 15);
    const uint32_t lseg = (lane >> 4) * 16;
    const uint32_t aoff = (wm + lrow) * ROWB + lseg;
    const uint32_t boff = (wn + lrow) * ROWB + lseg;

    if (tid == 0) {
#pragma unroll
        for (int s = 0; s < NSTG; s++) MBARRIER_INIT(smem_u32(&mbar[s]), 256);
    }
    __syncthreads();

    // threads 0-127 copy A rows, threads 128-255 copy B rows (128B each)
    auto issue = [&](int s, int kt) {
        const uint32_t m = smem_u32(&mbar[s]);
        const uint32_t st = sbase + s * STAGE;
        arrive_tx(m, 128u);
        if (tid < 128) {
            blk_cpy(st + tid * ROWB, A + (size_t)(bm + tid) * lda + kt * BKT, m);
        } else {
            const int r = tid - 128;
            blk_cpy(st + ABYTES + r * ROWB, B + (size_t)(bn + r) * ldb + kt * BKT, m);
        }
    };

    issue(0, 0);
    issue(1, 1);

    for (int kt = 0; kt < NK; kt++) {
        const int s = kt % NSTG;
        MBARRIER_WAIT_PARITY(smem_u32(&mbar[s]), (kt / NSTG) & 1);

        const uint32_t sA = sbase + s * STAGE + aoff;
        const uint32_t sB = sbase + s * STAGE + ABYTES + boff;
#pragma unroll
        for (int kk = 0; kk < 4; kk++) {
            uint32_t a[4][4], b[4][2];
#pragma unroll
            for (int mi = 0; mi < 4; mi++)
                LDSM_X4(a[mi][0], a[mi][1], a[mi][2], a[mi][3],
                        sA + mi * (16 * ROWB) + kk * 32);
#pragma unroll
            for (int j = 0; j < 2; j++) {
                uint32_t r0, r1, r2, r3;
                LDSM_X4(r0, r1, r2, r3, sB + j * (16 * ROWB) + kk * 32);
                b[2 * j][0] = r0;     b[2 * j][1] = r2;
                b[2 * j + 1][0] = r1; b[2 * j + 1][1] = r3;
            }
#pragma unroll
            for (int mi = 0; mi < 4; mi++)
#pragma unroll
                for (int ni = 0; ni < 4; ni++)
                    mma8(acc[mi][ni], a[mi], b[ni]);
        }
        __syncthreads();   // all warps done with stage s before it is refilled
        if (kt + 2 < NK) issue((kt + 2) % NSTG, kt + 2);
    }
}

// fragment -> global coordinates helper values
#define EPI_SETUP()                                        \
    const int tid = threadIdx.x;                           \
    const int wid = tid >> 5, lane = tid & 31;             \
    const int gid = lane >> 2, tig = lane & 3;             \
    const int wm = (wid & 1) * 64, wn = (wid >> 1) * 32;   \
    const int bm = blockIdx.y * BM, bn = blockIdx.x * BN;  \
    (void)bm; (void)bn;

// ---------------- GEMM kernels ---------------------------------------------------------

// q/k/v = round_tf32((x_r @ W^T + b) * scale);  q folds 1/(T*sqrt(H)) = 1/32
__global__ __launch_bounds__(256, 2) void qkv_tc(const float* __restrict__ bq,
                                                 const float* __restrict__ bk,
                                                 const float* __restrict__ bv) {
    EPI_SETUP();
    const float* W; const float* bias; float* out; float scale;
    if (blockIdx.z == 0)      { W = g_wq; bias = bq; out = g_q; scale = 1.0f / 32.0f; }
    else if (blockIdx.z == 1) { W = g_wk; bias = bk; out = g_k; scale = 1.0f; }
    else                      { W = g_wv; bias = bv; out = g_v; scale = 1.0f; }

    float acc[4][4][4];
    gemm_loop(g_xr, W, Hh, Hh, Hh, bm, bn, acc);

#pragma unroll
    for (int mi = 0; mi < 4; mi++) {
        const int r0 = bm + wm + mi * 16 + gid;
        float* o0 = out + (size_t)r0 * Hh;
        float* o1 = o0 + 8 * Hh;
#pragma unroll
        for (int ni = 0; ni < 4; ni++) {
            const int col = bn + wn + ni * 8 + 2 * tig;
            float2 bv2 = *(const float2*)(bias + col);
            float2 w0, w1;
            w0.x = tf32r((acc[mi][ni][0] + bv2.x) * scale);
            w0.y = tf32r((acc[mi][ni][1] + bv2.y) * scale);
            w1.x = tf32r((acc[mi][ni][2] + bv2.x) * scale);
            w1.y = tf32r((acc[mi][ni][3] + bv2.y) * scale);
            *(float2*)(o0 + col) = w0;
            *(float2*)(o1 + col) = w1;
        }
    }
}

// scores = q @ k^T + attn_bias, masked -> attn buffer (pre-softmax fp32)
__global__ __launch_bounds__(256, 2) void scores_tc(const float* __restrict__ attn_bias,
                                                    const int* __restrict__ mask,
                                                    float* __restrict__ attn) {
    EPI_SETUP();
    const int b = blockIdx.z;
    float acc[4][4][4];
    gemm_loop(g_q + (size_t)b * Ss * Hh, g_k + (size_t)b * Ss * Hh,
              Hh, Hh, Hh, bm, bn, acc);

#pragma unroll
    for (int mi = 0; mi < 4; mi++) {
        const int r0 = bm + wm + mi * 16 + gid;
        const int r1 = r0 + 8;
        float* c0 = attn + ((size_t)b * Ss + r0) * Ss;
        float* c1 = attn + ((size_t)b * Ss + r1) * Ss;
        const float* ab0 = attn_bias + ((size_t)b * Ss + r0) * Ss;
        const float* ab1 = attn_bias + ((size_t)b * Ss + r1) * Ss;
        const int* m0 = mask + (size_t)r0 * Ss;
        const int* m1 = mask + (size_t)r1 * Ss;
#pragma unroll
        for (int ni = 0; ni < 4; ni++) {
            const int col = bn + wn + ni * 8 + 2 * tig;
            float2 b0 = *(const float2*)(ab0 + col);
            float2 b1 = *(const float2*)(ab1 + col);
            int2 k0 = *(const int2*)(m0 + col);
            int2 k1 = *(const int2*)(m1 + col);
            float2 w0, w1;
            w0.x = k0.x ? acc[mi][ni][0] + b0.x : NEGV;
            w0.y = k0.y ? acc[mi][ni][1] + b0.y : NEGV;
            w1.x = k1.x ? acc[mi][ni][2] + b1.x : NEGV;
            w1.y = k1.y ? acc[mi][ni][3] + b1.y : NEGV;
            *(float2*)(c0 + col) = w0;
            *(float2*)(c1 + col) = w1;
        }
    }
}

// ctx = round_tf32(attn @ vT^T)
__global__ __launch_bounds__(256, 2) void av_tc(const float* __restrict__ attn) {
    EPI_SETUP();
    const int b = blockIdx.z;
    float acc[4][4][4];
    gemm_loop(attn + (size_t)b * Ss * Ss, g_vt + (size_t)b * Hh * Ss,
              Ss, Ss, Ss, bm, bn, acc);

#pragma unroll
    for (int mi = 0; mi < 4; mi++) {
        const int r0 = bm + wm + mi * 16 + gid;
        float* o0 = g_ctx + ((size_t)b * Ss + r0) * Hh;
        float* o1 = o0 + 8 * Hh;
#pragma unroll
        for (int ni = 0; ni < 4; ni++) {
            const int col = bn + wn + ni * 8 + 2 * tig;
            float2 w0, w1;
            w0.x = tf32r(acc[mi][ni][0]);
            w0.y = tf32r(acc[mi][ni][1]);
            w1.x = tf32r(acc[mi][ni][2]);
            w1.y = tf32r(acc[mi][ni][3]);
            *(float2*)(o0 + col) = w0;
            *(float2*)(o1 + col) = w1;
        }
    }
}

// out = ctx @ Wa^T + ba + residual(x)
__global__ __launch_bounds__(256, 2) void proj_tc(const float* __restrict__ ba,
                                                  const float* __restrict__ x,
                                                  float* __restrict__ out) {
    EPI_SETUP();
    float acc[4][4][4];
    gemm_loop(g_ctx, g_wa, Hh, Hh, Hh, bm, bn, acc);

#pragma unroll
    for (int mi = 0; mi < 4; mi++) {
        const int r0 = bm + wm + mi * 16 + gid;
        float* o0 = out + (size_t)r0 * Hh;
        float* o1 = o0 + 8 * Hh;
        const float* x0 = x + (size_t)r0 * Hh;
        const float* x1 = x0 + 8 * Hh;
#pragma unroll
        for (int ni = 0; ni < 4; ni++) {
            const int col = bn + wn + ni * 8 + 2 * tig;
            float2 bv2 = *(const float2*)(ba + col);
            float2 r0v = *(const float2*)(x0 + col);
            float2 r1v = *(const float2*)(x1 + col);
            float2 w0, w1;
            w0.x = acc[mi][ni][0] + bv2.x + r0v.x;
            w0.y = acc[mi][ni][1] + bv2.y + r0v.y;
            w1.x = acc[mi][ni][2] + bv2.x + r1v.x;
            w1.y = acc[mi][ni][3] + bv2.y + r1v.y;
            *(float2*)(o0 + col) = w0;
            *(float2*)(o1 + col) = w1;
        }
    }
}

// ---------------- small kernels ----------------------------------------------------------

// single fused tf32-rounding copy of x, Wq, Wk, Wv, Wa (1 launch)
__global__ __launch_bounds__(256) void rcopy_all(const float4* __restrict__ x,
                                                 const float4* __restrict__ wq,
                                                 const float4* __restrict__ wk,
                                                 const float4* __restrict__ wv,
                                                 const float4* __restrict__ wa) {
    const int NX = (Bb * Ss * Hh) / 4;        // 1048576
    const int NW = (Hh * Hh) / 4;             // 262144
    int i = blockIdx.x * blockDim.x + threadIdx.x;
    const float4* s;
    float4* d;
    if (i < NX) {
        s = x + i; d = (float4*)g_xr + i;
    } else {
        int u = i - NX;
        int w = u / NW, idx = u - w * NW;
        const float4* srcs[4] = {wq, wk, wv, wa};
        float4* dsts[4] = {(float4*)g_wq, (float4*)g_wk, (float4*)g_wv, (float4*)g_wa};
        s = srcs[w] + idx; d = dsts[w] + idx;
    }
    float4 v = *s;
    v.x = tf32r(v.x); v.y = tf32r(v.y); v.z = tf32r(v.z); v.w = tf32r(v.w);
    *d = v;
}

// vt[b][h][s] = v[b][s][h]
__global__ void vtrans_kernel() {
    __shared__ float t[32][33];
    const int b = blockIdx.z;
    const int s0 = blockIdx.x * 32, h0 = blockIdx.y * 32;
    const float* src = g_v + (size_t)b * Ss * Hh;
    float* dst = g_vt + (size_t)b * Hh * Ss;
    const int tx = threadIdx.x, ty = threadIdx.y;
#pragma unroll
    for (int i = 0; i < 32; i += 8)
        t[ty + i][tx] = src[(size_t)(s0 + ty + i) * Hh + h0 + tx];
    __syncthreads();
#pragma unroll
    for (int i = 0; i < 32; i += 8)
        dst[(size_t)(h0 + ty + i) * Ss + s0 + tx] = t[tx][ty + i];
}

__device__ __forceinline__ float warpMax(float v) {
#pragma unroll
    for (int o = 16; o; o >>= 1) v = fmaxf(v, __shfl_xor_sync(0xffffffffu, v, o));
    return v;
}
__device__ __forceinline__ float warpSum(float v) {
#pragma unroll
    for (int o = 16; o; o >>= 1) v += __shfl_xor_sync(0xffffffffu, v, o);
    return v;
}
__device__ __forceinline__ float blockMax(float v) {
    __shared__ float sh[8];
    v = warpMax(v);
    if ((threadIdx.x & 31) == 0) sh[threadIdx.x >> 5] = v;
    __syncthreads();
    float r = fmaxf(fmaxf(fmaxf(sh[0], sh[1]), fmaxf(sh[2], sh[3])),
                    fmaxf(fmaxf(sh[4], sh[5]), fmaxf(sh[6], sh[7])));
    __syncthreads();
    return r;
}
__device__ __forceinline__ float blockSum(float v) {
    __shared__ float sh[8];
    v = warpSum(v);
    if ((threadIdx.x & 31) == 0) sh[threadIdx.x >> 5] = v;
    __syncthreads();
    float r = sh[0] + sh[1] + sh[2] + sh[3] + sh[4] + sh[5] + sh[6] + sh[7];
    __syncthreads();
    return r;
}

// softmax over S=2048 (one 256-thread block per row); output rounded to tf32
__global__ __launch_bounds__(256) void softmax_kernel(float* __restrict__ attn) {
    size_t row = blockIdx.x;
    float4* p = (float4*)(attn + row * Ss);
    int tid = threadIdx.x;
    float4 v0 = p[tid];
    float4 v1 = p[tid + 256];
    float m = fmaxf(fmaxf(fmaxf(v0.x, v0.y), fmaxf(v0.z, v0.w)),
                    fmaxf(fmaxf(v1.x, v1.y), fmaxf(v1.z, v1.w)));
    m = blockMax(m);
    v0.x = __expf(v0.x - m); v0.y = __expf(v0.y - m);
    v0.z = __expf(v0.z - m); v0.w = __expf(v0.w - m);
    v1.x = __expf(v1.x - m); v1.y = __expf(v1.y - m);
    v1.z = __expf(v1.z - m); v1.w = __expf(v1.w - m);
    float s = v0.x + v0.y + v0.z + v0.w + v1.x + v1.y + v1.z + v1.w;
    s = blockSum(s);
    float inv = 1.0f / s;
    v0.x = tf32r(v0.x * inv); v0.y = tf32r(v0.y * inv);
    v0.z = tf32r(v0.z * inv); v0.w = tf32r(v0.w * inv);
    v1.x = tf32r(v1.x * inv); v1.y = tf32r(v1.y * inv);
    v1.z = tf32r(v1.z * inv); v1.w = tf32r(v1.w * inv);
    p[tid] = v0;
    p[tid + 256] = v1;
}

// in-place LayerNorm over H=1024 (biased variance, eps=1e-6)
__global__ __launch_bounds__(256) void ln_kernel(float* __restrict__ out,
                                                 const float* __restrict__ gamma,
                                                 const float* __restrict__ beta) {
    size_t row = blockIdx.x;
    float4* p = (float4*)(out + row * Hh);
    int tid = threadIdx.x;
    float4 v = p[tid];
    float s = v.x + v.y + v.z + v.w;
    s = blockSum(s);
    float mu = s * (1.0f / Hh);
    float dx = v.x - mu, dy = v.y - mu, dz = v.z - mu, dw = v.w - mu;
    float sq = dx * dx + dy * dy + dz * dz + dw * dw;
    sq = blockSum(sq);
    float rstd = rsqrtf(sq * (1.0f / Hh) + 1e-6f);
    float4 g = ((const float4*)gamma)[tid];
    float4 bt = ((const float4*)beta)[tid];
    v.x = dx * rstd * g.x + bt.x;
    v.y = dy * rstd * g.y + bt.y;
    v.z = dz * rstd * g.z + bt.z;
    v.w = dw * rstd * g.w + bt.w;
    p[tid] = v;
}

// ---------------- launch --------------------------------------------------------------
extern "C" void kernel_launch(void* const* d_in, const int* in_sizes, int n_in,
                              void* d_out, int out_size) {
    const float* x         = (const float*)d_in[0];
    const int*   mask      = (const int*)  d_in[1];
    const float* attn_bias = (const float*)d_in[2];
    const float* Wq = (const float*)d_in[3];  const float* bq = (const float*)d_in[4];
    const float* Wk = (const float*)d_in[5];  const float* bk = (const float*)d_in[6];
    const float* Wv = (const float*)d_in[7];  const float* bv = (const float*)d_in[8];
    const float* Wa = (const float*)d_in[9];  const float* ba = (const float*)d_in[10];
    const float* gamma = (const float*)d_in[11];
    const float* beta  = (const float*)d_in[12];

    float* out  = (float*)d_out;
    float* attn = out + (size_t)Bb * Ss * Hh;   // tuple (out, attn)

    cudaFuncSetAttribute(qkv_tc,    cudaFuncAttributeMaxDynamicSharedMemorySize, DYN_SMEM);
    cudaFuncSetAttribute(scores_tc, cudaFuncAttributeMaxDynamicSharedMemorySize, DYN_SMEM);
    cudaFuncSetAttribute(av_tc,     cudaFuncAttributeMaxDynamicSharedMemorySize, DYN_SMEM);
    cudaFuncSetAttribute(proj_tc,   cudaFuncAttributeMaxDynamicSharedMemorySize, DYN_SMEM);

    // 1 launch: round all GEMM operands to nearest-tf32
    int n4 = (Bb * Ss * Hh + 4 * Hh * Hh) / 4;
    rcopy_all<<<(n4 + 255) / 256, 256>>>((const float4*)x, (const float4*)Wq,
                                         (const float4*)Wk, (const float4*)Wv,
                                         (const float4*)Wa);

    qkv_tc<<<dim3(Hh / BN, (Bb * Ss) / BM, 3), 256, DYN_SMEM>>>(bq, bk, bv);
    vtrans_kernel<<<dim3(Ss / 32, Hh / 32, Bb), dim3(32, 8)>>>();
    scores_tc<<<dim3(Ss / BN, Ss / BM, Bb), 256, DYN_SMEM>>>(attn_bias, mask, attn);
    softmax_kernel<<<Bb * Ss, 256>>>(attn);
    av_tc<<<dim3(Hh / BN, Ss / BM, Bb), 256, DYN_SMEM>>>(attn);
    proj_tc<<<dim3(Hh / BN, (Bb * Ss) / BM), 256, DYN_SMEM>>>(ba, x, out);
    ln_kernel<<<Bb * Ss, 256>>>(out, gamma, beta);
}

// round 13
// speedup vs baseline: 1.1657x; 1.0499x over previous
#include <cuda_runtime.h>
#include <cstdint>
#include <math.h>

#define Bb 8
#define Ss 2048
#define Hh 1024
#define NEGV (-1e12f)

// ---------------- mma.sync tf32 GEMM configuration -----------------------------------
// 128x128 CTA tile, 512 threads (16 warps, 32x32 warp tiles), 3-stage bulk-copy pipeline,
// 110.6 KB smem x 2 CTAs/SM = 32 warps/SM = 8 warps/SMSP.
// R12 lever: latency-bound at 4 warps/SMSP (all pipes ~40-45%, T=3780cyc vs 1536 needs);
// halve acc regs (32x32 warp tile -> 32 acc) so 1024 threads/SM fit the register file.
constexpr int BM = 128, BN = 128, BKT = 32;
constexpr int ROWB = 36 * 4;                       // smem row pitch: 32 floats + 4 pad = 144B
constexpr int ABYTES = BM * ROWB;                  // 18432
constexpr int BBYTES = BN * ROWB;                  // 18432
constexpr int STAGE  = ABYTES + BBYTES;            // 36864
constexpr int NSTG   = 3;
constexpr int DYN_SMEM = NSTG * STAGE;             // 110592

// ---------------- scratch (static device memory) -------------------------------------
__device__ float g_xr [(size_t)Bb * Ss * Hh];
__device__ float g_q  [(size_t)Bb * Ss * Hh];
__device__ float g_k  [(size_t)Bb * Ss * Hh];
__device__ float g_v  [(size_t)Bb * Ss * Hh];
__device__ float g_vt [(size_t)Bb * Ss * Hh];
__device__ float g_ctx[(size_t)Bb * Ss * Hh];
__device__ float g_wq[Hh * Hh], g_wk[Hh * Hh], g_wv[Hh * Hh], g_wa[Hh * Hh];

// ---------------- helpers --------------------------------------------------------------
__device__ __forceinline__ uint32_t smem_u32(const void* p) {
    uint32_t a;
    asm("{ .reg .u64 t; cvta.to.shared.u64 t, %1; cvt.u32.u64 %0, t; }" : "=r"(a) : "l"(p));
    return a;
}
__device__ __forceinline__ float tf32r(float x) {
    uint32_t u;
    asm("cvt.rna.tf32.f32 %0, %1;" : "=r"(u) : "f"(x));
    return __uint_as_float(u);
}

#define MBARRIER_INIT(addr, cnt) \
    asm volatile("mbarrier.init.shared.b64 [%0], %1;" :: "r"((uint32_t)(addr)), "r"((uint32_t)(cnt)) : "memory")

#define MBARRIER_WAIT_PARITY(mbar_smem_addr, phase_parity) do {                         \
    uint32_t _mbar = (uint32_t)(mbar_smem_addr);                                        \
    uint32_t _parity = (uint32_t)(phase_parity);                                        \
    uint32_t _done;                                                                     \
    asm volatile("{\n\t.reg .pred p;\n\t"                                               \
        "mbarrier.try_wait.parity.acquire.cta.shared::cta.b64 p, [%1], %2;\n\t"         \
        "selp.b32 %0, 1, 0, p;\n\t}"                                                    \
        : "=r"(_done) : "r"(_mbar), "r"(_parity) : "memory");                           \
    if (!_done) {                                                                       \
        asm volatile("{\n\t.reg .pred P1;\n\t"                                          \
            "WAIT_LOOP_%=:\n\t"                                                         \
            "mbarrier.try_wait.parity.acquire.cta.shared::cta.b64 P1, [%0], %1, 0x989680;\n\t" \
            "@P1 bra.uni WAIT_DONE_%=;\n\t"                                             \
            "bra.uni WAIT_LOOP_%=;\n\t"                                                 \
            "WAIT_DONE_%=:\n\t}"                                                        \
            :: "r"(_mbar), "r"(_parity) : "memory");                                    \
    }                                                                                   \
} while (0)

// bulk async copy: 1 instruction per 128B row, completion via mbarrier tx-bytes
__device__ __forceinline__ void blk_cpy(uint32_t dst, const float* src, uint32_t mbar) {
    asm volatile(
        "cp.async.bulk.shared::cta.global.mbarrier::complete_tx::bytes [%0], [%1], %2, [%3];"
        :: "r"(dst), "l"(src), "r"(128), "r"(mbar) : "memory");
}
__device__ __forceinline__ void arrive_tx(uint32_t mbar, uint32_t bytes) {
    asm volatile("mbarrier.arrive.expect_tx.shared.b64 _, [%0], %1;"
                 :: "r"(mbar), "r"(bytes) : "memory");
}
__device__ __forceinline__ void arrive_plain(uint32_t mbar) {
    asm volatile("mbarrier.arrive.shared.b64 _, [%0];" :: "r"(mbar) : "memory");
}

#define LDSM_X4(r0, r1, r2, r3, addr) \
    asm volatile("ldmatrix.sync.aligned.m8n8.x4.shared.b16 {%0,%1,%2,%3}, [%4];" \
                 : "=r"(r0), "=r"(r1), "=r"(r2), "=r"(r3) : "r"(addr))

__device__ __forceinline__ void mma8(float d[4], const uint32_t a[4], const uint32_t b[2]) {
    asm volatile(
        "mma.sync.aligned.m16n8k8.row.col.f32.tf32.tf32.f32 "
        "{%0,%1,%2,%3}, {%4,%5,%6,%7}, {%8,%9}, {%0,%1,%2,%3};"
        : "+f"(d[0]), "+f"(d[1]), "+f"(d[2]), "+f"(d[3])
        : "r"(a[0]), "r"(a[1]), "r"(a[2]), "r"(a[3]), "r"(b[0]), "r"(b[1]));
}

// ---------------- GEMM mainloop: acc[2][4][4] = A[bm:bm+128] * B[bn:bn+128]^T ---------
// A: [M,K] row-major, B: [N,K] row-major (computes A @ B^T).
// 512 threads, 16 warps as 4(M) x 4(N); warp tile 32x32. Fragments via ldmatrix.x4.
__device__ __forceinline__ void gemm_loop(const float* __restrict__ A,
                                          const float* __restrict__ B,
                                          int K, int lda, int ldb, int bm, int bn,
                                          float acc[2][4][4]) {
    extern __shared__ __align__(16) char dsm[];
    __shared__ __align__(8) unsigned long long mbar[NSTG];
    const int tid = threadIdx.x;
    const int wid = tid >> 5, lane = tid & 31;
    const int wm = (wid & 3) * 32, wn = (wid >> 2) * 32;
    const int NK = K / BKT;

#pragma unroll
    for (int mi = 0; mi < 2; mi++)
#pragma unroll
        for (int ni = 0; ni < 4; ni++)
#pragma unroll
            for (int j = 0; j < 4; j++) acc[mi][ni][j] = 0.0f;

    const uint32_t sbase = smem_u32(dsm);
    // ldmatrix lane address parts (R11-verified mapping)
    const uint32_t lrow = (lane & 15);
    const uint32_t lseg = (lane >> 4) * 16;
    const uint32_t aoff = (wm + lrow) * ROWB + lseg;
    const uint32_t boff = (wn + lrow) * ROWB + lseg;

    if (tid == 0) {
#pragma unroll
        for (int s = 0; s < NSTG; s++) MBARRIER_INIT(smem_u32(&mbar[s]), 512);
    }
    __syncthreads();

    // threads 0-127 copy A rows, 128-255 copy B rows; everyone arrives
    auto issue = [&](int s, int kt) {
        const uint32_t m = smem_u32(&mbar[s]);
        const uint32_t st = sbase + s * STAGE;
        if (tid < 128) {
            arrive_tx(m, 128u);
            blk_cpy(st + tid * ROWB, A + (size_t)(bm + tid) * lda + kt * BKT, m);
        } else if (tid < 256) {
            const int r = tid - 128;
            arrive_tx(m, 128u);
            blk_cpy(st + ABYTES + r * ROWB, B + (size_t)(bn + r) * ldb + kt * BKT, m);
        } else {
            arrive_plain(m);
        }
    };

    issue(0, 0);
    issue(1, 1);

    for (int kt = 0; kt < NK; kt++) {
        const int s = kt % NSTG;
        MBARRIER_WAIT_PARITY(smem_u32(&mbar[s]), (kt / NSTG) & 1);

        const uint32_t sA = sbase + s * STAGE + aoff;
        const uint32_t sB = sbase + s * STAGE + ABYTES + boff;
#pragma unroll
        for (int kk = 0; kk < 4; kk++) {
            uint32_t a[2][4], b[4][2];
#pragma unroll
            for (int mi = 0; mi < 2; mi++)
                LDSM_X4(a[mi][0], a[mi][1], a[mi][2], a[mi][3],
                        sA + mi * (16 * ROWB) + kk * 32);
#pragma unroll
            for (int j = 0; j < 2; j++) {
                uint32_t r0, r1, r2, r3;
                LDSM_X4(r0, r1, r2, r3, sB + j * (16 * ROWB) + kk * 32);
                b[2 * j][0] = r0;     b[2 * j][1] = r2;
                b[2 * j + 1][0] = r1; b[2 * j + 1][1] = r3;
            }
#pragma unroll
            for (int mi = 0; mi < 2; mi++)
#pragma unroll
                for (int ni = 0; ni < 4; ni++)
                    mma8(acc[mi][ni], a[mi], b[ni]);
        }
        __syncthreads();   // all warps done with stage s before it is refilled
        if (kt + 2 < NK) issue((kt + 2) % NSTG, kt + 2);
    }
}

// fragment -> global coordinates helper values
#define EPI_SETUP()                                        \
    const int tid = threadIdx.x;                           \
    const int wid = tid >> 5, lane = tid & 31;             \
    const int gid = lane >> 2, tig = lane & 3;             \
    const int wm = (wid & 3) * 32, wn = (wid >> 2) * 32;   \
    const int bm = blockIdx.y * BM, bn = blockIdx.x * BN;  \
    (void)bm; (void)bn;

// ---------------- GEMM kernels ---------------------------------------------------------

// q/k/v = round_tf32((x_r @ W^T + b) * scale);  q folds 1/(T*sqrt(H)) = 1/32
__global__ __launch_bounds__(512, 2) void qkv_tc(const float* __restrict__ bq,
                                                 const float* __restrict__ bk,
                                                 const float* __restrict__ bv) {
    EPI_SETUP();
    const float* W; const float* bias; float* out; float scale;
    if (blockIdx.z == 0)      { W = g_wq; bias = bq; out = g_q; scale = 1.0f / 32.0f; }
    else if (blockIdx.z == 1) { W = g_wk; bias = bk; out = g_k; scale = 1.0f; }
    else                      { W = g_wv; bias = bv; out = g_v; scale = 1.0f; }

    float acc[2][4][4];
    gemm_loop(g_xr, W, Hh, Hh, Hh, bm, bn, acc);

#pragma unroll
    for (int mi = 0; mi < 2; mi++) {
        const int r0 = bm + wm + mi * 16 + gid;
        float* o0 = out + (size_t)r0 * Hh;
        float* o1 = o0 + 8 * Hh;
#pragma unroll
        for (int ni = 0; ni < 4; ni++) {
            const int col = bn + wn + ni * 8 + 2 * tig;
            float2 bv2 = *(const float2*)(bias + col);
            float2 w0, w1;
            w0.x = tf32r((acc[mi][ni][0] + bv2.x) * scale);
            w0.y = tf32r((acc[mi][ni][1] + bv2.y) * scale);
            w1.x = tf32r((acc[mi][ni][2] + bv2.x) * scale);
            w1.y = tf32r((acc[mi][ni][3] + bv2.y) * scale);
            *(float2*)(o0 + col) = w0;
            *(float2*)(o1 + col) = w1;
        }
    }
}

// scores = q @ k^T + attn_bias, masked -> attn buffer (pre-softmax fp32)
__global__ __launch_bounds__(512, 2) void scores_tc(const float* __restrict__ attn_bias,
                                                    const int* __restrict__ mask,
                                                    float* __restrict__ attn) {
    EPI_SETUP();
    const int b = blockIdx.z;
    float acc[2][4][4];
    gemm_loop(g_q + (size_t)b * Ss * Hh, g_k + (size_t)b * Ss * Hh,
              Hh, Hh, Hh, bm, bn, acc);

#pragma unroll
    for (int mi = 0; mi < 2; mi++) {
        const int r0 = bm + wm + mi * 16 + gid;
        const int r1 = r0 + 8;
        float* c0 = attn + ((size_t)b * Ss + r0) * Ss;
        float* c1 = attn + ((size_t)b * Ss + r1) * Ss;
        const float* ab0 = attn_bias + ((size_t)b * Ss + r0) * Ss;
        const float* ab1 = attn_bias + ((size_t)b * Ss + r1) * Ss;
        const int* m0 = mask + (size_t)r0 * Ss;
        const int* m1 = mask + (size_t)r1 * Ss;
#pragma unroll
        for (int ni = 0; ni < 4; ni++) {
            const int col = bn + wn + ni * 8 + 2 * tig;
            float2 b0 = *(const float2*)(ab0 + col);
            float2 b1 = *(const float2*)(ab1 + col);
            int2 k0 = *(const int2*)(m0 + col);
            int2 k1 = *(const int2*)(m1 + col);
            float2 w0, w1;
            w0.x = k0.x ? acc[mi][ni][0] + b0.x : NEGV;
            w0.y = k0.y ? acc[mi][ni][1] + b0.y : NEGV;
            w1.x = k1.x ? acc[mi][ni][2] + b1.x : NEGV;
            w1.y = k1.y ? acc[mi][ni][3] + b1.y : NEGV;
            *(float2*)(c0 + col) = w0;
            *(float2*)(c1 + col) = w1;
        }
    }
}

// ctx = round_tf32(attn @ vT^T)
__global__ __launch_bounds__(512, 2) void av_tc(const float* __restrict__ attn) {
    EPI_SETUP();
    const int b = blockIdx.z;
    float acc[2][4][4];
    gemm_loop(attn + (size_t)b * Ss * Ss, g_vt + (size_t)b * Hh * Ss,
              Ss, Ss, Ss, bm, bn, acc);

#pragma unroll
    for (int mi = 0; mi < 2; mi++) {
        const int r0 = bm + wm + mi * 16 + gid;
        float* o0 = g_ctx + ((size_t)b * Ss + r0) * Hh;
        float* o1 = o0 + 8 * Hh;
#pragma unroll
        for (int ni = 0; ni < 4; ni++) {
            const int col = bn + wn + ni * 8 + 2 * tig;
            float2 w0, w1;
            w0.x = tf32r(acc[mi][ni][0]);
            w0.y = tf32r(acc[mi][ni][1]);
            w1.x = tf32r(acc[mi][ni][2]);
            w1.y = tf32r(acc[mi][ni][3]);
            *(float2*)(o0 + col) = w0;
            *(float2*)(o1 + col) = w1;
        }
    }
}

// out = ctx @ Wa^T + ba + residual(x)
__global__ __launch_bounds__(512, 2) void proj_tc(const float* __restrict__ ba,
                                                  const float* __restrict__ x,
                                                  float* __restrict__ out) {
    EPI_SETUP();
    float acc[2][4][4];
    gemm_loop(g_ctx, g_wa, Hh, Hh, Hh, bm, bn, acc);

#pragma unroll
    for (int mi = 0; mi < 2; mi++) {
        const int r0 = bm + wm + mi * 16 + gid;
        float* o0 = out + (size_t)r0 * Hh;
        float* o1 = o0 + 8 * Hh;
        const float* x0 = x + (size_t)r0 * Hh;
        const float* x1 = x0 + 8 * Hh;
#pragma unroll
        for (int ni = 0; ni < 4; ni++) {
            const int col = bn + wn + ni * 8 + 2 * tig;
            float2 bv2 = *(const float2*)(ba + col);
            float2 r0v = *(const float2*)(x0 + col);
            float2 r1v = *(const float2*)(x1 + col);
            float2 w0, w1;
            w0.x = acc[mi][ni][0] + bv2.x + r0v.x;
            w0.y = acc[mi][ni][1] + bv2.y + r0v.y;
            w1.x = acc[mi][ni][2] + bv2.x + r1v.x;
            w1.y = acc[mi][ni][3] + bv2.y + r1v.y;
            *(float2*)(o0 + col) = w0;
            *(float2*)(o1 + col) = w1;
        }
    }
}

// ---------------- small kernels ----------------------------------------------------------

// single fused tf32-rounding copy of x, Wq, Wk, Wv, Wa (1 launch)
__global__ __launch_bounds__(256) void rcopy_all(const float4* __restrict__ x,
                                                 const float4* __restrict__ wq,
                                                 const float4* __restrict__ wk,
                                                 const float4* __restrict__ wv,
                                                 const float4* __restrict__ wa) {
    const int NX = (Bb * Ss * Hh) / 4;        // 1048576
    const int NW = (Hh * Hh) / 4;             // 262144
    int i = blockIdx.x * blockDim.x + threadIdx.x;
    const float4* s;
    float4* d;
    if (i < NX) {
        s = x + i; d = (float4*)g_xr + i;
    } else {
        int u = i - NX;
        int w = u / NW, idx = u - w * NW;
        const float4* srcs[4] = {wq, wk, wv, wa};
        float4* dsts[4] = {(float4*)g_wq, (float4*)g_wk, (float4*)g_wv, (float4*)g_wa};
        s = srcs[w] + idx; d = dsts[w] + idx;
    }
    float4 v = *s;
    v.x = tf32r(v.x); v.y = tf32r(v.y); v.z = tf32r(v.z); v.w = tf32r(v.w);
    *d = v;
}

// vt[b][h][s] = v[b][s][h]
__global__ void vtrans_kernel() {
    __shared__ float t[32][33];
    const int b = blockIdx.z;
    const int s0 = blockIdx.x * 32, h0 = blockIdx.y * 32;
    const float* src = g_v + (size_t)b * Ss * Hh;
    float* dst = g_vt + (size_t)b * Hh * Ss;
    const int tx = threadIdx.x, ty = threadIdx.y;
#pragma unroll
    for (int i = 0; i < 32; i += 8)
        t[ty + i][tx] = src[(size_t)(s0 + ty + i) * Hh + h0 + tx];
    __syncthreads();
#pragma unroll
    for (int i = 0; i < 32; i += 8)
        dst[(size_t)(h0 + ty + i) * Ss + s0 + tx] = t[tx][ty + i];
}

__device__ __forceinline__ float warpMax(float v) {
#pragma unroll
    for (int o = 16; o; o >>= 1) v = fmaxf(v, __shfl_xor_sync(0xffffffffu, v, o));
    return v;
}
__device__ __forceinline__ float warpSum(float v) {
#pragma unroll
    for (int o = 16; o; o >>= 1) v += __shfl_xor_sync(0xffffffffu, v, o);
    return v;
}
__device__ __forceinline__ float blockMax(float v) {
    __shared__ float sh[8];
    v = warpMax(v);
    if ((threadIdx.x & 31) == 0) sh[threadIdx.x >> 5] = v;
    __syncthreads();
    float r = fmaxf(fmaxf(fmaxf(sh[0], sh[1]), fmaxf(sh[2], sh[3])),
                    fmaxf(fmaxf(sh[4], sh[5]), fmaxf(sh[6], sh[7])));
    __syncthreads();
    return r;
}
__device__ __forceinline__ float blockSum(float v) {
    __shared__ float sh[8];
    v = warpSum(v);
    if ((threadIdx.x & 31) == 0) sh[threadIdx.x >> 5] = v;
    __syncthreads();
    float r = sh[0] + sh[1] + sh[2] + sh[3] + sh[4] + sh[5] + sh[6] + sh[7];
    __syncthreads();
    return r;
}

// softmax over S=2048 (one 256-thread block per row); output rounded to tf32
__global__ __launch_bounds__(256) void softmax_kernel(float* __restrict__ attn) {
    size_t row = blockIdx.x;
    float4* p = (float4*)(attn + row * Ss);
    int tid = threadIdx.x;
    float4 v0 = p[tid];
    float4 v1 = p[tid + 256];
    float m = fmaxf(fmaxf(fmaxf(v0.x, v0.y), fmaxf(v0.z, v0.w)),
                    fmaxf(fmaxf(v1.x, v1.y), fmaxf(v1.z, v1.w)));
    m = blockMax(m);
    v0.x = __expf(v0.x - m); v0.y = __expf(v0.y - m);
    v0.z = __expf(v0.z - m); v0.w = __expf(v0.w - m);
    v1.x = __expf(v1.x - m); v1.y = __expf(v1.y - m);
    v1.z = __expf(v1.z - m); v1.w = __expf(v1.w - m);
    float s = v0.x + v0.y + v0.z + v0.w + v1.x + v1.y + v1.z + v1.w;
    s = blockSum(s);
    float inv = 1.0f / s;
    v0.x = tf32r(v0.x * inv); v0.y = tf32r(v0.y * inv);
    v0.z = tf32r(v0.z * inv); v0.w = tf32r(v0.w * inv);
    v1.x = tf32r(v1.x * inv); v1.y = tf32r(v1.y * inv);
    v1.z = tf32r(v1.z * inv); v1.w = tf32r(v1.w * inv);
    p[tid] = v0;
    p[tid + 256] = v1;
}

// in-place LayerNorm over H=1024 (biased variance, eps=1e-6)
__global__ __launch_bounds__(256) void ln_kernel(float* __restrict__ out,
                                                 const float* __restrict__ gamma,
                                                 const float* __restrict__ beta) {
    size_t row = blockIdx.x;
    float4* p = (float4*)(out + row * Hh);
    int tid = threadIdx.x;
    float4 v = p[tid];
    float s = v.x + v.y + v.z + v.w;
    s = blockSum(s);
    float mu = s * (1.0f / Hh);
    float dx = v.x - mu, dy = v.y - mu, dz = v.z - mu, dw = v.w - mu;
    float sq = dx * dx + dy * dy + dz * dz + dw * dw;
    sq = blockSum(sq);
    float rstd = rsqrtf(sq * (1.0f / Hh) + 1e-6f);
    float4 g = ((const float4*)gamma)[tid];
    float4 bt = ((const float4*)beta)[tid];
    v.x = dx * rstd * g.x + bt.x;
    v.y = dy * rstd * g.y + bt.y;
    v.z = dz * rstd * g.z + bt.z;
    v.w = dw * rstd * g.w + bt.w;
    p[tid] = v;
}

// ---------------- launch --------------------------------------------------------------
extern "C" void kernel_launch(void* const* d_in, const int* in_sizes, int n_in,
                              void* d_out, int out_size) {
    const float* x         = (const float*)d_in[0];
    const int*   mask      = (const int*)  d_in[1];
    const float* attn_bias = (const float*)d_in[2];
    const float* Wq = (const float*)d_in[3];  const float* bq = (const float*)d_in[4];
    const float* Wk = (const float*)d_in[5];  const float* bk = (const float*)d_in[6];
    const float* Wv = (const float*)d_in[7];  const float* bv = (const float*)d_in[8];
    const float* Wa = (const float*)d_in[9];  const float* ba = (const float*)d_in[10];
    const float* gamma = (const float*)d_in[11];
    const float* beta  = (const float*)d_in[12];

    float* out  = (float*)d_out;
    float* attn = out + (size_t)Bb * Ss * Hh;   // tuple (out, attn)

    cudaFuncSetAttribute(qkv_tc,    cudaFuncAttributeMaxDynamicSharedMemorySize, DYN_SMEM);
    cudaFuncSetAttribute(scores_tc, cudaFuncAttributeMaxDynamicSharedMemorySize, DYN_SMEM);
    cudaFuncSetAttribute(av_tc,     cudaFuncAttributeMaxDynamicSharedMemorySize, DYN_SMEM);
    cudaFuncSetAttribute(proj_tc,   cudaFuncAttributeMaxDynamicSharedMemorySize, DYN_SMEM);

    // 1 launch: round all GEMM operands to nearest-tf32
    int n4 = (Bb * Ss * Hh + 4 * Hh * Hh) / 4;
    rcopy_all<<<(n4 + 255) / 256, 256>>>((const float4*)x, (const float4*)Wq,
                                         (const float4*)Wk, (const float4*)Wv,
                                         (const float4*)Wa);

    qkv_tc<<<dim3(Hh / BN, (Bb * Ss) / BM, 3), 512, DYN_SMEM>>>(bq, bk, bv);
    vtrans_kernel<<<dim3(Ss / 32, Hh / 32, Bb), dim3(32, 8)>>>();
    scores_tc<<<dim3(Ss / BN, Ss / BM, Bb), 512, DYN_SMEM>>>(attn_bias, mask, attn);
    softmax_kernel<<<Bb * Ss, 256>>>(attn);
    av_tc<<<dim3(Hh / BN, Ss / BM, Bb), 512, DYN_SMEM>>>(attn);
    proj_tc<<<dim3(Hh / BN, (Bb * Ss) / BM), 512, DYN_SMEM>>>(ba, x, out);
    ln_kernel<<<Bb * Ss, 256>>>(out, gamma, beta);
}

// round 14
// speedup vs baseline: 2.0800x; 1.7844x over previous
#include <cuda_runtime.h>
#include <cuda_fp16.h>
#include <cstdint>
#include <math.h>

#define Bb 8
#define Ss 2048
#define Hh 1024
#define NEGV (-1e12f)

// ---------------- mma.sync fp16 GEMM configuration -----------------------------------
// 128x128 CTA tile, 512 threads (16 warps, 32x32 warp tiles), 3-stage bulk-copy pipeline,
// 110.6 KB smem x 2 CTAs/SM. R13 lever: tf32 m16n8k8 -> fp16 m16n8k16 (same 11-bit
// mantissa, 2x FLOP/instr, half bytes): HMMA count, LDSM bytes, smem bytes, L2/DRAM
// traffic all halve per FLOP. BKT doubles to 64 fp16 (=128B rows, same bulk copies).
constexpr int BM = 128, BN = 128, BKT = 64;
constexpr int ROWB = 144;                          // 128B data + 16B pad (conflict-free)
constexpr int ABYTES = BM * ROWB;                  // 18432
constexpr int BBYTES = BN * ROWB;                  // 18432
constexpr int STAGE  = ABYTES + BBYTES;            // 36864
constexpr int NSTG   = 3;
constexpr int DYN_SMEM = NSTG * STAGE;             // 110592

// ---------------- scratch (static device memory, fp16 intermediates) -----------------
__device__ __half g_xr [(size_t)Bb * Ss * Hh];
__device__ __half g_q  [(size_t)Bb * Ss * Hh];
__device__ __half g_k  [(size_t)Bb * Ss * Hh];
__device__ __half g_v  [(size_t)Bb * Ss * Hh];
__device__ __half g_vt [(size_t)Bb * Ss * Hh];
__device__ __half g_ctx[(size_t)Bb * Ss * Hh];
__device__ __half g_attnh[(size_t)Bb * Ss * Ss];   // fp16 softmax(attn) for AV GEMM
__device__ __half g_wq[Hh * Hh], g_wk[Hh * Hh], g_wv[Hh * Hh], g_wa[Hh * Hh];

// ---------------- helpers --------------------------------------------------------------
__device__ __forceinline__ uint32_t smem_u32(const void* p) {
    uint32_t a;
    asm("{ .reg .u64 t; cvta.to.shared.u64 t, %1; cvt.u32.u64 %0, t; }" : "=r"(a) : "l"(p));
    return a;
}

#define MBARRIER_INIT(addr, cnt) \
    asm volatile("mbarrier.init.shared.b64 [%0], %1;" :: "r"((uint32_t)(addr)), "r"((uint32_t)(cnt)) : "memory")

#define MBARRIER_WAIT_PARITY(mbar_smem_addr, phase_parity) do {                         \
    uint32_t _mbar = (uint32_t)(mbar_smem_addr);                                        \
    uint32_t _parity = (uint32_t)(phase_parity);                                        \
    uint32_t _done;                                                                     \
    asm volatile("{\n\t.reg .pred p;\n\t"                                               \
        "mbarrier.try_wait.parity.acquire.cta.shared::cta.b64 p, [%1], %2;\n\t"         \
        "selp.b32 %0, 1, 0, p;\n\t}"                                                    \
        : "=r"(_done) : "r"(_mbar), "r"(_parity) : "memory");                           \
    if (!_done) {                                                                       \
        asm volatile("{\n\t.reg .pred P1;\n\t"                                          \
            "WAIT_LOOP_%=:\n\t"                                                         \
            "mbarrier.try_wait.parity.acquire.cta.shared::cta.b64 P1, [%0], %1, 0x989680;\n\t" \
            "@P1 bra.uni WAIT_DONE_%=;\n\t"                                             \
            "bra.uni WAIT_LOOP_%=;\n\t"                                                 \
            "WAIT_DONE_%=:\n\t}"                                                        \
            :: "r"(_mbar), "r"(_parity) : "memory");                                    \
    }                                                                                   \
} while (0)

// bulk async copy: 1 instruction per 128B row, completion via mbarrier tx-bytes
__device__ __forceinline__ void blk_cpy(uint32_t dst, const void* src, uint32_t mbar) {
    asm volatile(
        "cp.async.bulk.shared::cta.global.mbarrier::complete_tx::bytes [%0], [%1], %2, [%3];"
        :: "r"(dst), "l"(src), "r"(128), "r"(mbar) : "memory");
}
__device__ __forceinline__ void arrive_tx(uint32_t mbar, uint32_t bytes) {
    asm volatile("mbarrier.arrive.expect_tx.shared.b64 _, [%0], %1;"
                 :: "r"(mbar), "r"(bytes) : "memory");
}
__device__ __forceinline__ void arrive_plain(uint32_t mbar) {
    asm volatile("mbarrier.arrive.shared.b64 _, [%0];" :: "r"(mbar) : "memory");
}

#define LDSM_X4(r0, r1, r2, r3, addr) \
    asm volatile("ldmatrix.sync.aligned.m8n8.x4.shared.b16 {%0,%1,%2,%3}, [%4];" \
                 : "=r"(r0), "=r"(r1), "=r"(r2), "=r"(r3) : "r"(addr))

__device__ __forceinline__ void mma16(float d[4], const uint32_t a[4], const uint32_t b[2]) {
    asm volatile(
        "mma.sync.aligned.m16n8k16.row.col.f32.f16.f16.f32 "
        "{%0,%1,%2,%3}, {%4,%5,%6,%7}, {%8,%9}, {%0,%1,%2,%3};"
        : "+f"(d[0]), "+f"(d[1]), "+f"(d[2]), "+f"(d[3])
        : "r"(a[0]), "r"(a[1]), "r"(a[2]), "r"(a[3]), "r"(b[0]), "r"(b[1]));
}

// ---------------- GEMM mainloop: acc[2][4][4] = A[bm:bm+128] * B[bn:bn+128]^T ---------
// A: [M,K] row-major fp16, B: [N,K] row-major fp16 (computes A @ B^T).
// 512 threads, 16 warps as 4(M) x 4(N); warp tile 32x32. Fragments via ldmatrix.x4.
__device__ __forceinline__ void gemm_loop(const __half* __restrict__ A,
                                          const __half* __restrict__ B,
                                          int K, int lda, int ldb, int bm, int bn,
                                          float acc[2][4][4]) {
    extern __shared__ __align__(16) char dsm[];
    __shared__ __align__(8) unsigned long long mbar[NSTG];
    const int tid = threadIdx.x;
    const int wid = tid >> 5, lane = tid & 31;
    const int wm = (wid & 3) * 32, wn = (wid >> 2) * 32;
    const int NK = K / BKT;

#pragma unroll
    for (int mi = 0; mi < 2; mi++)
#pragma unroll
        for (int ni = 0; ni < 4; ni++)
#pragma unroll
            for (int j = 0; j < 4; j++) acc[mi][ni][j] = 0.0f;

    const uint32_t sbase = smem_u32(dsm);
    // ldmatrix lane addressing: lanes 0-15 -> rows 0-15 (k 0-7 bytes 0-15),
    // lanes 16-31 -> rows 0-15 with +16B (k 8-15). fp16: 16 rows x 32B per fragment.
    const uint32_t lrow = (lane & 15);
    const uint32_t lseg = (lane >> 4) * 16;
    const uint32_t aoff = (wm + lrow) * ROWB + lseg;
    const uint32_t boff = (wn + lrow) * ROWB + lseg;

    if (tid == 0) {
#pragma unroll
        for (int s = 0; s < NSTG; s++) MBARRIER_INIT(smem_u32(&mbar[s]), 512);
    }
    __syncthreads();

    // threads 0-127 copy A rows, 128-255 copy B rows (128B = 64 fp16 each)
    auto issue = [&](int s, int kt) {
        const uint32_t m = smem_u32(&mbar[s]);
        const uint32_t st = sbase + s * STAGE;
        if (tid < 128) {
            arrive_tx(m, 128u);
            blk_cpy(st + tid * ROWB, A + (size_t)(bm + tid) * lda + kt * BKT, m);
        } else if (tid < 256) {
            const int r = tid - 128;
            arrive_tx(m, 128u);
            blk_cpy(st + ABYTES + r * ROWB, B + (size_t)(bn + r) * ldb + kt * BKT, m);
        } else {
            arrive_plain(m);
        }
    };

    issue(0, 0);
    issue(1, 1);

    for (int kt = 0; kt < NK; kt++) {
        const int s = kt % NSTG;
        MBARRIER_WAIT_PARITY(smem_u32(&mbar[s]), (kt / NSTG) & 1);

        const uint32_t sA = sbase + s * STAGE + aoff;
        const uint32_t sB = sbase + s * STAGE + ABYTES + boff;
#pragma unroll
        for (int kk = 0; kk < 4; kk++) {   // 4 x k16 per 64-element ktile
            uint32_t a[2][4], b[4][2];
#pragma unroll
            for (int mi = 0; mi < 2; mi++)
                LDSM_X4(a[mi][0], a[mi][1], a[mi][2], a[mi][3],
                        sA + mi * (16 * ROWB) + kk * 32);
#pragma unroll
            for (int j = 0; j < 2; j++) {
                uint32_t r0, r1, r2, r3;
                LDSM_X4(r0, r1, r2, r3, sB + j * (16 * ROWB) + kk * 32);
                b[2 * j][0] = r0;     b[2 * j][1] = r2;
                b[2 * j + 1][0] = r1; b[2 * j + 1][1] = r3;
            }
#pragma unroll
            for (int mi = 0; mi < 2; mi++)
#pragma unroll
                for (int ni = 0; ni < 4; ni++)
                    mma16(acc[mi][ni], a[mi], b[ni]);
        }
        __syncthreads();   // all warps done with stage s before it is refilled
        if (kt + 2 < NK) issue((kt + 2) % NSTG, kt + 2);
    }
}

// fragment -> global coordinates helper values
#define EPI_SETUP()                                        \
    const int tid = threadIdx.x;                           \
    const int wid = tid >> 5, lane = tid & 31;             \
    const int gid = lane >> 2, tig = lane & 3;             \
    const int wm = (wid & 3) * 32, wn = (wid >> 2) * 32;   \
    const int bm = blockIdx.y * BM, bn = blockIdx.x * BN;  \
    (void)bm; (void)bn;

// ---------------- GEMM kernels ---------------------------------------------------------

// q/k/v = fp16(x_r @ W^T + b)   (q stored UNSCALED; 1/32 applied in scores epilogue)
__global__ __launch_bounds__(512, 2) void qkv_tc(const float* __restrict__ bq,
                                                 const float* __restrict__ bk,
                                                 const float* __restrict__ bv) {
    EPI_SETUP();
    const __half* W; const float* bias; __half* out;
    if (blockIdx.z == 0)      { W = g_wq; bias = bq; out = g_q; }
    else if (blockIdx.z == 1) { W = g_wk; bias = bk; out = g_k; }
    else                      { W = g_wv; bias = bv; out = g_v; }

    float acc[2][4][4];
    gemm_loop(g_xr, W, Hh, Hh, Hh, bm, bn, acc);

#pragma unroll
    for (int mi = 0; mi < 2; mi++) {
        const int r0 = bm + wm + mi * 16 + gid;
        __half* o0 = out + (size_t)r0 * Hh;
        __half* o1 = o0 + 8 * Hh;
#pragma unroll
        for (int ni = 0; ni < 4; ni++) {
            const int col = bn + wn + ni * 8 + 2 * tig;
            float2 bv2 = *(const float2*)(bias + col);
            __half2 w0 = __floats2half2_rn(acc[mi][ni][0] + bv2.x, acc[mi][ni][1] + bv2.y);
            __half2 w1 = __floats2half2_rn(acc[mi][ni][2] + bv2.x, acc[mi][ni][3] + bv2.y);
            *(__half2*)(o0 + col) = w0;
            *(__half2*)(o1 + col) = w1;
        }
    }
}

// scores = (q @ k^T)/32 + attn_bias, masked -> attn buffer (pre-softmax fp32)
__global__ __launch_bounds__(512, 2) void scores_tc(const float* __restrict__ attn_bias,
                                                    const int* __restrict__ mask,
                                                    float* __restrict__ attn) {
    EPI_SETUP();
    const int b = blockIdx.z;
    float acc[2][4][4];
    gemm_loop(g_q + (size_t)b * Ss * Hh, g_k + (size_t)b * Ss * Hh,
              Hh, Hh, Hh, bm, bn, acc);

    const float inv32 = 1.0f / 32.0f;
#pragma unroll
    for (int mi = 0; mi < 2; mi++) {
        const int r0 = bm + wm + mi * 16 + gid;
        const int r1 = r0 + 8;
        float* c0 = attn + ((size_t)b * Ss + r0) * Ss;
        float* c1 = attn + ((size_t)b * Ss + r1) * Ss;
        const float* ab0 = attn_bias + ((size_t)b * Ss + r0) * Ss;
        const float* ab1 = attn_bias + ((size_t)b * Ss + r1) * Ss;
        const int* m0 = mask + (size_t)r0 * Ss;
        const int* m1 = mask + (size_t)r1 * Ss;
#pragma unroll
        for (int ni = 0; ni < 4; ni++) {
            const int col = bn + wn + ni * 8 + 2 * tig;
            float2 b0 = *(const float2*)(ab0 + col);
            float2 b1 = *(const float2*)(ab1 + col);
            int2 k0 = *(const int2*)(m0 + col);
            int2 k1 = *(const int2*)(m1 + col);
            float2 w0, w1;
            w0.x = k0.x ? acc[mi][ni][0] * inv32 + b0.x : NEGV;
            w0.y = k0.y ? acc[mi][ni][1] * inv32 + b0.y : NEGV;
            w1.x = k1.x ? acc[mi][ni][2] * inv32 + b1.x : NEGV;
            w1.y = k1.y ? acc[mi][ni][3] * inv32 + b1.y : NEGV;
            *(float2*)(c0 + col) = w0;
            *(float2*)(c1 + col) = w1;
        }
    }
}

// ctx = fp16(attn @ vT^T)
__global__ __launch_bounds__(512, 2) void av_tc() {
    EPI_SETUP();
    const int b = blockIdx.z;
    float acc[2][4][4];
    gemm_loop(g_attnh + (size_t)b * Ss * Ss, g_vt + (size_t)b * Hh * Ss,
              Ss, Ss, Ss, bm, bn, acc);

#pragma unroll
    for (int mi = 0; mi < 2; mi++) {
        const int r0 = bm + wm + mi * 16 + gid;
        __half* o0 = g_ctx + ((size_t)b * Ss + r0) * Hh;
        __half* o1 = o0 + 8 * Hh;
#pragma unroll
        for (int ni = 0; ni < 4; ni++) {
            const int col = bn + wn + ni * 8 + 2 * tig;
            __half2 w0 = __floats2half2_rn(acc[mi][ni][0], acc[mi][ni][1]);
            __half2 w1 = __floats2half2_rn(acc[mi][ni][2], acc[mi][ni][3]);
            *(__half2*)(o0 + col) = w0;
            *(__half2*)(o1 + col) = w1;
        }
    }
}

// out = ctx @ Wa^T + ba + residual(x)   (fp32 output)
__global__ __launch_bounds__(512, 2) void proj_tc(const float* __restrict__ ba,
                                                  const float* __restrict__ x,
                                                  float* __restrict__ out) {
    EPI_SETUP();
    float acc[2][4][4];
    gemm_loop(g_ctx, g_wa, Hh, Hh, Hh, bm, bn, acc);

#pragma unroll
    for (int mi = 0; mi < 2; mi++) {
        const int r0 = bm + wm + mi * 16 + gid;
        float* o0 = out + (size_t)r0 * Hh;
        float* o1 = o0 + 8 * Hh;
        const float* x0 = x + (size_t)r0 * Hh;
        const float* x1 = x0 + 8 * Hh;
#pragma unroll
        for (int ni = 0; ni < 4; ni++) {
            const int col = bn + wn + ni * 8 + 2 * tig;
            float2 bv2 = *(const float2*)(ba + col);
            float2 r0v = *(const float2*)(x0 + col);
            float2 r1v = *(const float2*)(x1 + col);
            float2 w0, w1;
            w0.x = acc[mi][ni][0] + bv2.x + r0v.x;
            w0.y = acc[mi][ni][1] + bv2.y + r0v.y;
            w1.x = acc[mi][ni][2] + bv2.x + r1v.x;
            w1.y = acc[mi][ni][3] + bv2.y + r1v.y;
            *(float2*)(o0 + col) = w0;
            *(float2*)(o1 + col) = w1;
        }
    }
}

// ---------------- small kernels ----------------------------------------------------------

// fused fp32->fp16 convert of x, Wq, Wk, Wv, Wa (8 elements/thread)
__global__ __launch_bounds__(256) void rcopy_all(const float4* __restrict__ x,
                                                 const float4* __restrict__ wq,
                                                 const float4* __restrict__ wk,
                                                 const float4* __restrict__ wv,
                                                 const float4* __restrict__ wa) {
    const int NX = (Bb * Ss * Hh) / 8;        // 8-elem groups in x
    const int NW = (Hh * Hh) / 8;
    int i = blockIdx.x * blockDim.x + threadIdx.x;
    const float4* s;
    __half2* d;
    if (i < NX) {
        s = x + 2 * (size_t)i; d = (__half2*)g_xr + 4 * (size_t)i;
    } else {
        int u = i - NX;
        int w = u / NW, idx = u - w * NW;
        const float4* srcs[4] = {wq, wk, wv, wa};
        __half2* dsts[4] = {(__half2*)g_wq, (__half2*)g_wk, (__half2*)g_wv, (__half2*)g_wa};
        s = srcs[w] + 2 * (size_t)idx; d = dsts[w] + 4 * (size_t)idx;
    }
    float4 a = s[0], b2 = s[1];
    d[0] = __floats2half2_rn(a.x, a.y);
    d[1] = __floats2half2_rn(a.z, a.w);
    d[2] = __floats2half2_rn(b2.x, b2.y);
    d[3] = __floats2half2_rn(b2.z, b2.w);
}

// vt[b][h][s] = v[b][s][h]   (fp16)
__global__ void vtrans_kernel() {
    __shared__ __half t[32][33];
    const int b = blockIdx.z;
    const int s0 = blockIdx.x * 32, h0 = blockIdx.y * 32;
    const __half* src = g_v + (size_t)b * Ss * Hh;
    __half* dst = g_vt + (size_t)b * Hh * Ss;
    const int tx = threadIdx.x, ty = threadIdx.y;
#pragma unroll
    for (int i = 0; i < 32; i += 8)
        t[ty + i][tx] = src[(size_t)(s0 + ty + i) * Hh + h0 + tx];
    __syncthreads();
#pragma unroll
    for (int i = 0; i < 32; i += 8)
        dst[(size_t)(h0 + ty + i) * Ss + s0 + tx] = t[tx][ty + i];
}

__device__ __forceinline__ float warpMax(float v) {
#pragma unroll
    for (int o = 16; o; o >>= 1) v = fmaxf(v, __shfl_xor_sync(0xffffffffu, v, o));
    return v;
}
__device__ __forceinline__ float warpSum(float v) {
#pragma unroll
    for (int o = 16; o; o >>= 1) v += __shfl_xor_sync(0xffffffffu, v, o);
    return v;
}
__device__ __forceinline__ float blockMax(float v) {
    __shared__ float sh[8];
    v = warpMax(v);
    if ((threadIdx.x & 31) == 0) sh[threadIdx.x >> 5] = v;
    __syncthreads();
    float r = fmaxf(fmaxf(fmaxf(sh[0], sh[1]), fmaxf(sh[2], sh[3])),
                    fmaxf(fmaxf(sh[4], sh[5]), fmaxf(sh[6], sh[7])));
    __syncthreads();
    return r;
}
__device__ __forceinline__ float blockSum(float v) {
    __shared__ float sh[8];
    v = warpSum(v);
    if ((threadIdx.x & 31) == 0) sh[threadIdx.x >> 5] = v;
    __syncthreads();
    float r = sh[0] + sh[1] + sh[2] + sh[3] + sh[4] + sh[5] + sh[6] + sh[7];
    __syncthreads();
    return r;
}

// softmax over S=2048; writes canonical fp32 attn AND fp16 copy for the AV GEMM
__global__ __launch_bounds__(256) void softmax_kernel(float* __restrict__ attn) {
    size_t row = blockIdx.x;
    float4* p = (float4*)(attn + row * Ss);
    __half2* ph = (__half2*)(g_attnh + row * Ss);
    int tid = threadIdx.x;
    float4 v0 = p[tid];
    float4 v1 = p[tid + 256];
    float m = fmaxf(fmaxf(fmaxf(v0.x, v0.y), fmaxf(v0.z, v0.w)),
                    fmaxf(fmaxf(v1.x, v1.y), fmaxf(v1.z, v1.w)));
    m = blockMax(m);
    v0.x = __expf(v0.x - m); v0.y = __expf(v0.y - m);
    v0.z = __expf(v0.z - m); v0.w = __expf(v0.w - m);
    v1.x = __expf(v1.x - m); v1.y = __expf(v1.y - m);
    v1.z = __expf(v1.z - m); v1.w = __expf(v1.w - m);
    float s = v0.x + v0.y + v0.z + v0.w + v1.x + v1.y + v1.z + v1.w;
    s = blockSum(s);
    float inv = 1.0f / s;
    v0.x *= inv; v0.y *= inv; v0.z *= inv; v0.w *= inv;
    v1.x *= inv; v1.y *= inv; v1.z *= inv; v1.w *= inv;
    p[tid] = v0;
    p[tid + 256] = v1;
    ph[2 * tid]           = __floats2half2_rn(v0.x, v0.y);
    ph[2 * tid + 1]       = __floats2half2_rn(v0.z, v0.w);
    ph[2 * (tid + 256)]     = __floats2half2_rn(v1.x, v1.y);
    ph[2 * (tid + 256) + 1] = __floats2half2_rn(v1.z, v1.w);
}

// in-place LayerNorm over H=1024 (biased variance, eps=1e-6)
__global__ __launch_bounds__(256) void ln_kernel(float* __restrict__ out,
                                                 const float* __restrict__ gamma,
                                                 const float* __restrict__ beta) {
    size_t row = blockIdx.x;
    float4* p = (float4*)(out + row * Hh);
    int tid = threadIdx.x;
    float4 v = p[tid];
    float s = v.x + v.y + v.z + v.w;
    s = blockSum(s);
    float mu = s * (1.0f / Hh);
    float dx = v.x - mu, dy = v.y - mu, dz = v.z - mu, dw = v.w - mu;
    float sq = dx * dx + dy * dy + dz * dz + dw * dw;
    sq = blockSum(sq);
    float rstd = rsqrtf(sq * (1.0f / Hh) + 1e-6f);
    float4 g = ((const float4*)gamma)[tid];
    float4 bt = ((const float4*)beta)[tid];
    v.x = dx * rstd * g.x + bt.x;
    v.y = dy * rstd * g.y + bt.y;
    v.z = dz * rstd * g.z + bt.z;
    v.w = dw * rstd * g.w + bt.w;
    p[tid] = v;
}

// ---------------- launch --------------------------------------------------------------
extern "C" void kernel_launch(void* const* d_in, const int* in_sizes, int n_in,
                              void* d_out, int out_size) {
    const float* x         = (const float*)d_in[0];
    const int*   mask      = (const int*)  d_in[1];
    const float* attn_bias = (const float*)d_in[2];
    const float* Wq = (const float*)d_in[3];  const float* bq = (const float*)d_in[4];
    const float* Wk = (const float*)d_in[5];  const float* bk = (const float*)d_in[6];
    const float* Wv = (const float*)d_in[7];  const float* bv = (const float*)d_in[8];
    const float* Wa = (const float*)d_in[9];  const float* ba = (const float*)d_in[10];
    const float* gamma = (const float*)d_in[11];
    const float* beta  = (const float*)d_in[12];

    float* out  = (float*)d_out;
    float* attn = out + (size_t)Bb * Ss * Hh;   // tuple (out, attn)

    cudaFuncSetAttribute(qkv_tc,    cudaFuncAttributeMaxDynamicSharedMemorySize, DYN_SMEM);
    cudaFuncSetAttribute(scores_tc, cudaFuncAttributeMaxDynamicSharedMemorySize, DYN_SMEM);
    cudaFuncSetAttribute(av_tc,     cudaFuncAttributeMaxDynamicSharedMemorySize, DYN_SMEM);
    cudaFuncSetAttribute(proj_tc,   cudaFuncAttributeMaxDynamicSharedMemorySize, DYN_SMEM);

    // 1 launch: convert all GEMM operands to fp16
    int ng = (Bb * Ss * Hh + 4 * Hh * Hh) / 8;
    rcopy_all<<<(ng + 255) / 256, 256>>>((const float4*)x, (const float4*)Wq,
                                         (const float4*)Wk, (const float4*)Wv,
                                         (const float4*)Wa);

    qkv_tc<<<dim3(Hh / BN, (Bb * Ss) / BM, 3), 512, DYN_SMEM>>>(bq, bk, bv);
    vtrans_kernel<<<dim3(Ss / 32, Hh / 32, Bb), dim3(32, 8)>>>();
    scores_tc<<<dim3(Ss / BN, Ss / BM, Bb), 512, DYN_SMEM>>>(attn_bias, mask, attn);
    softmax_kernel<<<Bb * Ss, 256>>>(attn);
    av_tc<<<dim3(Hh / BN, Ss / BM, Bb), 512, DYN_SMEM>>>();
    proj_tc<<<dim3(Hh / BN, (Bb * Ss) / BM), 512, DYN_SMEM>>>(ba, x, out);
    ln_kernel<<<Bb * Ss, 256>>>(out, gamma, beta);
}